// round 1
// baseline (speedup 1.0000x reference)
#include <cuda_runtime.h>
#include <math.h>

#define SEQ 2048
#define HID 4096
#define KVD 1024
#define NH  32
#define NKV 8
#define HD  128

// Scratch (device globals — no allocation allowed)
__device__ float g_Q[SEQ * HID];   // 32 MB
__device__ float g_K[SEQ * KVD];   // 8 MB
__device__ float g_V[SEQ * KVD];   // 8 MB
__device__ float g_A[SEQ * HID];   // 32 MB (attention output, head-major cols)

// ---------------------------------------------------------------------------
// NT GEMM: C[m,n] = sum_k A[m*K+k] * B[n*K+k]   (A: [M,K] rm, B: [N,K] rm)
// BM=BN=128, BK=16, 256 threads, 8x8 per-thread tile.
// Requires M%128==0, N%128==0, K%16==0 (true for all 4 calls).
// ---------------------------------------------------------------------------
__global__ __launch_bounds__(256) void sgemm_nt(const float* __restrict__ A,
                                                const float* __restrict__ B,
                                                float* __restrict__ C,
                                                int M, int N, int K)
{
    constexpr int BM = 128, BN = 128, BK = 16;
    __shared__ float As[BK][BM];
    __shared__ float Bs[BK][BN];

    const int tid = threadIdx.x;
    const int bm = blockIdx.y * BM;
    const int bn = blockIdx.x * BN;
    const int tx = tid & 15;    // 0..15 -> N
    const int ty = tid >> 4;    // 0..15 -> M

    const float* Ab = A + (size_t)bm * K;
    const float* Bb = B + (size_t)bn * K;

    float acc[8][8];
#pragma unroll
    for (int i = 0; i < 8; i++)
#pragma unroll
        for (int j = 0; j < 8; j++) acc[i][j] = 0.0f;

    for (int k0 = 0; k0 < K; k0 += BK) {
        // load A,B tiles: 128x16 each, via float4 (512 vec per tile, 2 per thread)
#pragma unroll
        for (int i = 0; i < 2; ++i) {
            int idx = tid + i * 256;          // 0..511
            int row = idx >> 2;               // 0..127
            int kc  = (idx & 3) * 4;          // 0,4,8,12
            float4 va = *(const float4*)&Ab[(size_t)row * K + k0 + kc];
            As[kc + 0][row] = va.x; As[kc + 1][row] = va.y;
            As[kc + 2][row] = va.z; As[kc + 3][row] = va.w;
            float4 vb = *(const float4*)&Bb[(size_t)row * K + k0 + kc];
            Bs[kc + 0][row] = vb.x; Bs[kc + 1][row] = vb.y;
            Bs[kc + 2][row] = vb.z; Bs[kc + 3][row] = vb.w;
        }
        __syncthreads();

#pragma unroll
        for (int kk = 0; kk < BK; ++kk) {
            float a[8], b[8];
#pragma unroll
            for (int i = 0; i < 8; i++) a[i] = As[kk][ty * 8 + i];
#pragma unroll
            for (int j = 0; j < 8; j++) b[j] = Bs[kk][tx * 8 + j];
#pragma unroll
            for (int i = 0; i < 8; i++)
#pragma unroll
                for (int j = 0; j < 8; j++)
                    acc[i][j] = fmaf(a[i], b[j], acc[i][j]);
        }
        __syncthreads();
    }

#pragma unroll
    for (int i = 0; i < 8; i++) {
        float4* cp = (float4*)&C[(size_t)(bm + ty * 8 + i) * N + bn + tx * 8];
        cp[0] = make_float4(acc[i][0], acc[i][1], acc[i][2], acc[i][3]);
        cp[1] = make_float4(acc[i][4], acc[i][5], acc[i][6], acc[i][7]);
    }
}

// ---------------------------------------------------------------------------
// RoPE in-place. data: [SEQ, nheads*128]. Position = seq index (matches
// broadcast arange in the reference).
// out[d<64]  = x[d]*cos - x[d+64]*sin
// out[d>=64] = x[d]*cos + x[d-64]*sin,  angle = s * theta^(-2j/128), j = d%64
// ---------------------------------------------------------------------------
__global__ void rope_kernel(float* __restrict__ data, int nheads)
{
    int idx = blockIdx.x * blockDim.x + threadIdx.x;
    int total = SEQ * nheads * 64;
    if (idx >= total) return;
    int j = idx & 63;
    int h = (idx >> 6) % nheads;
    int s = idx / (64 * nheads);

    // inv_freq = theta^(-2j/128) = 2^(-j/64 * log2(1e6))
    const float LOG2_THETA = 19.931568569324174f;   // log2(1e6)
    float inv = exp2f(-(float)j * (LOG2_THETA / 64.0f));
    float ang = (float)s * inv;
    float sn, cs;
    sincosf(ang, &sn, &cs);

    float* p = data + (size_t)s * (nheads * 128) + h * 128 + j;
    float x0 = p[0], x1 = p[64];
    p[0]  = x0 * cs - x1 * sn;
    p[64] = x1 * cs + x0 * sn;
}

// ---------------------------------------------------------------------------
// fp32 flash attention. BQ=BK=64, D=128. grid = (32 qblocks, 32 heads),
// 256 threads. Online softmax. Writes g_A[s, head*128 + d].
// ---------------------------------------------------------------------------
struct FlashSmem {
    float Q[64][129];   // pad 129: conflict-light scalar reads
    float K[64][129];
    float V[64][132];   // pad 132: keeps rows 16B-aligned for float4 reads
    float S[64][68];
    float m[64];
    float l[64];
    float alpha[64];
};

__global__ __launch_bounds__(256) void flash_attn()
{
    extern __shared__ char smem_raw[];
    FlashSmem* sh = (FlashSmem*)smem_raw;

    const int tid  = threadIdx.x;
    const int head = blockIdx.y;
    const int qb   = gridDim.x - 1 - blockIdx.x;   // longest blocks first
    const int kvh  = head >> 2;
    const int qbase = qb * 64;

    // thread mappings
    const int ti = tid >> 4, tj = tid & 15;   // S compute: 4x4 tile at (ti*4, tj*4)
    const int r  = tid >> 2, c  = tid & 3;    // softmax: row r, keys c*16..c*16+15
    const int rr = tid >> 3, dc = tid & 7;    // PV: rows rr & rr+32, dims dc*16..+16

    // load Q block (64 x 128)
    for (int idx = tid; idx < 64 * 32; idx += 256) {
        int row = idx >> 5;
        int c4  = (idx & 31) * 4;
        float4 v = *(const float4*)&g_Q[(size_t)(qbase + row) * HID + head * HD + c4];
        sh->Q[row][c4 + 0] = v.x; sh->Q[row][c4 + 1] = v.y;
        sh->Q[row][c4 + 2] = v.z; sh->Q[row][c4 + 3] = v.w;
    }
    if (tid < 64) { sh->m[tid] = -1e30f; sh->l[tid] = 0.0f; }

    float acc0[16], acc1[16];
#pragma unroll
    for (int i = 0; i < 16; i++) { acc0[i] = 0.0f; acc1[i] = 0.0f; }

    __syncthreads();

    const float scale = 0.08838834764831845f;  // 1/sqrt(128)

    for (int kb = 0; kb <= qb; ++kb) {
        const int kbase = kb * 64;
        // load K, V blocks
        for (int idx = tid; idx < 64 * 32; idx += 256) {
            int row = idx >> 5;
            int c4  = (idx & 31) * 4;
            float4 vk = *(const float4*)&g_K[(size_t)(kbase + row) * KVD + kvh * HD + c4];
            sh->K[row][c4 + 0] = vk.x; sh->K[row][c4 + 1] = vk.y;
            sh->K[row][c4 + 2] = vk.z; sh->K[row][c4 + 3] = vk.w;
            float4 vv = *(const float4*)&g_V[(size_t)(kbase + row) * KVD + kvh * HD + c4];
            sh->V[row][c4 + 0] = vv.x; sh->V[row][c4 + 1] = vv.y;
            sh->V[row][c4 + 2] = vv.z; sh->V[row][c4 + 3] = vv.w;
        }
        __syncthreads();

        // ---- S = Q K^T (each thread: 4x4) ----
        float s[4][4];
#pragma unroll
        for (int a = 0; a < 4; a++)
#pragma unroll
            for (int b = 0; b < 4; b++) s[a][b] = 0.0f;

#pragma unroll 4
        for (int d = 0; d < 128; ++d) {
            float qa[4], kv[4];
#pragma unroll
            for (int a = 0; a < 4; a++) qa[a] = sh->Q[ti * 4 + a][d];
#pragma unroll
            for (int b = 0; b < 4; b++) kv[b] = sh->K[tj * 4 + b][d];
#pragma unroll
            for (int a = 0; a < 4; a++)
#pragma unroll
                for (int b = 0; b < 4; b++)
                    s[a][b] = fmaf(qa[a], kv[b], s[a][b]);
        }

        const bool diag = (kb == qb);
#pragma unroll
        for (int a = 0; a < 4; a++)
#pragma unroll
            for (int b = 0; b < 4; b++) {
                float val = s[a][b] * scale;
                if (diag && (tj * 4 + b > ti * 4 + a)) val = -1e30f;
                sh->S[ti * 4 + a][tj * 4 + b] = val;
            }
        __syncthreads();

        // ---- online softmax (4 lanes per row) ----
        float sv[16];
        float mloc = -1e30f;
#pragma unroll
        for (int j = 0; j < 16; j++) {
            sv[j] = sh->S[r][c * 16 + j];
            mloc = fmaxf(mloc, sv[j]);
        }
        mloc = fmaxf(mloc, __shfl_xor_sync(0xffffffffu, mloc, 1));
        mloc = fmaxf(mloc, __shfl_xor_sync(0xffffffffu, mloc, 2));
        float mo = sh->m[r];
        float mn = fmaxf(mo, mloc);
        float sum = 0.0f;
#pragma unroll
        for (int j = 0; j < 16; j++) {
            float p = __expf(sv[j] - mn);
            sum += p;
            sh->S[r][c * 16 + j] = p;
        }
        sum += __shfl_xor_sync(0xffffffffu, sum, 1);
        sum += __shfl_xor_sync(0xffffffffu, sum, 2);
        if (c == 0) {
            float al = __expf(mo - mn);
            sh->alpha[r] = al;
            sh->m[r] = mn;
            sh->l[r] = sh->l[r] * al + sum;
        }
        __syncthreads();

        // ---- O = alpha*O + P V ----
        float a0 = sh->alpha[rr], a1 = sh->alpha[rr + 32];
#pragma unroll
        for (int i = 0; i < 16; i++) { acc0[i] *= a0; acc1[i] *= a1; }

#pragma unroll 2
        for (int k = 0; k < 64; ++k) {
            float p0 = sh->S[rr][k];
            float p1 = sh->S[rr + 32][k];
            const float4* vp = (const float4*)&sh->V[k][dc * 16];
#pragma unroll
            for (int i4 = 0; i4 < 4; ++i4) {
                float4 v = vp[i4];
                acc0[i4 * 4 + 0] = fmaf(p0, v.x, acc0[i4 * 4 + 0]);
                acc0[i4 * 4 + 1] = fmaf(p0, v.y, acc0[i4 * 4 + 1]);
                acc0[i4 * 4 + 2] = fmaf(p0, v.z, acc0[i4 * 4 + 2]);
                acc0[i4 * 4 + 3] = fmaf(p0, v.w, acc0[i4 * 4 + 3]);
                acc1[i4 * 4 + 0] = fmaf(p1, v.x, acc1[i4 * 4 + 0]);
                acc1[i4 * 4 + 1] = fmaf(p1, v.y, acc1[i4 * 4 + 1]);
                acc1[i4 * 4 + 2] = fmaf(p1, v.z, acc1[i4 * 4 + 2]);
                acc1[i4 * 4 + 3] = fmaf(p1, v.w, acc1[i4 * 4 + 3]);
            }
        }
        __syncthreads();
    }

    // ---- normalize + write ----
    float inv0 = 1.0f / sh->l[rr];
    float inv1 = 1.0f / sh->l[rr + 32];
    float* o0 = &g_A[(size_t)(qbase + rr) * HID + head * HD + dc * 16];
    float* o1 = &g_A[(size_t)(qbase + rr + 32) * HID + head * HD + dc * 16];
#pragma unroll
    for (int i4 = 0; i4 < 4; ++i4) {
        ((float4*)o0)[i4] = make_float4(acc0[i4 * 4 + 0] * inv0, acc0[i4 * 4 + 1] * inv0,
                                        acc0[i4 * 4 + 2] * inv0, acc0[i4 * 4 + 3] * inv0);
        ((float4*)o1)[i4] = make_float4(acc1[i4 * 4 + 0] * inv1, acc1[i4 * 4 + 1] * inv1,
                                        acc1[i4 * 4 + 2] * inv1, acc1[i4 * 4 + 3] * inv1);
    }
}

// ---------------------------------------------------------------------------
extern "C" void kernel_launch(void* const* d_in, const int* in_sizes, int n_in,
                              void* d_out, int out_size)
{
    const float* X  = (const float*)d_in[0];
    // d_in[1] = position_ids (arange; derived from seq index instead)
    const float* Wq = (const float*)d_in[2];
    const float* Wk = (const float*)d_in[3];
    const float* Wv = (const float*)d_in[4];
    const float* Wo = (const float*)d_in[5];
    float* out = (float*)d_out;

    float *Qp, *Kp, *Vp, *Ap;
    cudaGetSymbolAddress((void**)&Qp, g_Q);
    cudaGetSymbolAddress((void**)&Kp, g_K);
    cudaGetSymbolAddress((void**)&Vp, g_V);
    cudaGetSymbolAddress((void**)&Ap, g_A);

    dim3 blk(256);
    // QKV projections
    sgemm_nt<<<dim3(HID / 128, SEQ / 128), blk>>>(X, Wq, Qp, SEQ, HID, HID);
    sgemm_nt<<<dim3(KVD / 128, SEQ / 128), blk>>>(X, Wk, Kp, SEQ, KVD, HID);
    sgemm_nt<<<dim3(KVD / 128, SEQ / 128), blk>>>(X, Wv, Vp, SEQ, KVD, HID);

    // RoPE
    rope_kernel<<<(SEQ * NH * 64 + 255) / 256, 256>>>(Qp, NH);
    rope_kernel<<<(SEQ * NKV * 64 + 255) / 256, 256>>>(Kp, NKV);

    // Attention
    cudaFuncSetAttribute(flash_attn, cudaFuncAttributeMaxDynamicSharedMemorySize,
                         (int)sizeof(FlashSmem));
    flash_attn<<<dim3(SEQ / 64, NH), blk, sizeof(FlashSmem)>>>();

    // Output projection
    sgemm_nt<<<dim3(HID / 128, SEQ / 128), blk>>>(Ap, Wo, out, SEQ, HID, HID);
}